// round 4
// baseline (speedup 1.0000x reference)
#include <cuda_runtime.h>
#include <cuda_bf16.h>
#include <stdint.h>
#include <math.h>

#define HEADS 12
#define HEAD_SIZE 64
#define HIDDEN 768
#define EPROJ 1536
#define SEQ 1024
#define NB 8
#define NEGV 1000000000000.0f

// bf16 staging buffers
__device__ __align__(128) __nv_bfloat16 g_xb[NB * SEQ * HIDDEN];   // [8192][768]
__device__ __align__(128) __nv_bfloat16 g_wt[EPROJ * HIDDEN];      // [1536][768] = W^T
__device__ __align__(128) __nv_bfloat16 g_q[NB * HEADS * SEQ * HEAD_SIZE];
__device__ __align__(128) __nv_bfloat16 g_k[NB * HEADS * SEQ * HEAD_SIZE];

#define SWZ(o) ((o) ^ (((o) >> 3) & 0x70))

__device__ __forceinline__ uint32_t smem_u32(const void* p) {
    uint32_t a;
    asm("{ .reg .u64 t; cvta.to.shared.u64 t, %1; cvt.u32.u64 %0, t; }"
        : "=r"(a) : "l"(p));
    return a;
}

__device__ __forceinline__ void ldmx4(uint32_t* r, uint32_t addr) {
    asm volatile("ldmatrix.sync.aligned.m8n8.x4.shared.b16 {%0,%1,%2,%3}, [%4];"
                 : "=r"(r[0]), "=r"(r[1]), "=r"(r[2]), "=r"(r[3]) : "r"(addr));
}
__device__ __forceinline__ void ldmx2(uint32_t* r, uint32_t addr) {
    asm volatile("ldmatrix.sync.aligned.m8n8.x2.shared.b16 {%0,%1}, [%2];"
                 : "=r"(r[0]), "=r"(r[1]) : "r"(addr));
}
__device__ __forceinline__ void mma16816(float* c, const uint32_t* a,
                                         const uint32_t* b) {
    asm volatile(
        "mma.sync.aligned.m16n8k16.row.col.f32.bf16.bf16.f32 "
        "{%0,%1,%2,%3}, {%4,%5,%6,%7}, {%8,%9}, {%0,%1,%2,%3};"
        : "+f"(c[0]), "+f"(c[1]), "+f"(c[2]), "+f"(c[3])
        : "r"(a[0]), "r"(a[1]), "r"(a[2]), "r"(a[3]), "r"(b[0]), "r"(b[1]));
}

#define CP_ASYNC16(dst, src) \
    asm volatile("cp.async.cg.shared.global [%0], [%1], 16;" \
                 :: "r"(dst), "l"(src) : "memory")
#define CP_COMMIT asm volatile("cp.async.commit_group;" ::: "memory")
#define CP_WAIT1 asm volatile("cp.async.wait_group 1;" ::: "memory")
#define CP_WAIT0 asm volatile("cp.async.wait_group 0;" ::: "memory")

// ---------------------------------------------------------------------------
// conversion kernels
// ---------------------------------------------------------------------------
__global__ void conv_x_kernel(const float* __restrict__ x) {
    int i = blockIdx.x * blockDim.x + threadIdx.x;  // float4 index
    float4 v = ((const float4*)x)[i];
    __nv_bfloat162 lo, hi;
    lo.x = __float2bfloat16(v.x); lo.y = __float2bfloat16(v.y);
    hi.x = __float2bfloat16(v.z); hi.y = __float2bfloat16(v.w);
    uint2 u;
    u.x = *(uint32_t*)&lo; u.y = *(uint32_t*)&hi;
    ((uint2*)g_xb)[i] = u;
}

__global__ void conv_wt_kernel(const float* __restrict__ W) {
    __shared__ float t[32][33];
    int bx = blockIdx.x * 32, by = blockIdx.y * 32;
#pragma unroll
    for (int j = 0; j < 4; j++)
        t[threadIdx.y + j * 8][threadIdx.x] =
            W[(size_t)(by + threadIdx.y + j * 8) * EPROJ + bx + threadIdx.x];
    __syncthreads();
#pragma unroll
    for (int j = 0; j < 4; j++)
        g_wt[(size_t)(bx + threadIdx.y + j * 8) * HIDDEN + by + threadIdx.x] =
            __float2bfloat16(t[threadIdx.x][threadIdx.y + j * 8]);
}

// ---------------------------------------------------------------------------
// Kernel 1: proj = x @ W (+bias) then RoPE -> g_q / g_k (bf16)
// CTA tile 128x128, K pipelined in chunks of 64 via cp.async double buffer.
// 8 warps: 2(m) x 4(n), warp tile 64x32.
// Dynamic smem: stage s at s*32768 (A 16KB + B 16KB), aux at 65536.
// ---------------------------------------------------------------------------
#define PROJ_SMEM (65536 + 640)

__global__ void proj_kernel(const float* __restrict__ bias) {
    extern __shared__ __align__(128) char dsm[];
    float* s_inv = (float*)(dsm + 65536);
    float* s_bias = (float*)(dsm + 65536 + 128);

    const int tid = threadIdx.x;
    const int lane = tid & 31;
    const int wid = tid >> 5;
    const int wm = wid & 1;   // 0..1
    const int wn = wid >> 1;  // 0..3
    const int h = blockIdx.x;             // head tile (12)
    const int rowBase = blockIdx.y * 128; // token rows
    const int colBase = h * 128;

    if (tid < 32) s_inv[tid] = exp2f(-(float)(2 * tid) * (13.287712379549449f / 64.0f));
    if (tid < 128) s_bias[tid] = bias[colBase + tid];

    const uint32_t sbase = smem_u32(dsm);

    // Per-thread load slots (4 uint4 per tile).
    int lr[4], lc[4];
    uint32_t lso[4];
#pragma unroll
    for (int i = 0; i < 4; i++) {
        int e = tid + i * 256;
        lr[i] = e >> 3;
        lc[i] = (e & 7) * 8;              // bf16 col offset
        lso[i] = SWZ((uint32_t)(lr[i] * 128 + (e & 7) * 16));
    }

    // issue loads for chunk ch into stage buffer
#define PROJ_LOAD(ch)                                                        \
    {                                                                        \
        const int k0_ = (ch) * 64;                                           \
        const uint32_t sb_ = sbase + ((ch) & 1) * 32768;                     \
        _Pragma("unroll") for (int i = 0; i < 4; i++) {                      \
            CP_ASYNC16(sb_ + lso[i],                                         \
                       g_xb + (size_t)(rowBase + lr[i]) * HIDDEN + k0_ + lc[i]); \
            CP_ASYNC16(sb_ + 16384 + lso[i],                                 \
                       g_wt + (size_t)(colBase + lr[i]) * HIDDEN + k0_ + lc[i]); \
        }                                                                    \
        CP_COMMIT;                                                           \
    }

    float acc[4][4][4] = {};

    PROJ_LOAD(0);
    for (int ch = 0; ch < 12; ch++) {
        if (ch < 11) { PROJ_LOAD(ch + 1); CP_WAIT1; }
        else { CP_WAIT0; }
        __syncthreads();

        const uint32_t sAb = sbase + (ch & 1) * 32768;
        const uint32_t sBb = sAb + 16384;
#pragma unroll
        for (int ks = 0; ks < 4; ks++) {
            uint32_t aF[4][4], bF[4][2];
#pragma unroll
            for (int mi = 0; mi < 4; mi++) {
                int r = wm * 64 + mi * 16 + (lane & 15);
                int cc = ks * 2 + (lane >> 4);
                ldmx4(aF[mi], sAb + SWZ((uint32_t)(r * 128 + cc * 16)));
            }
#pragma unroll
            for (int ni = 0; ni < 4; ni++) {
                int l = lane & 15;
                int r = wn * 32 + ni * 8 + (l & 7);
                int cc = ks * 2 + (l >> 3);
                ldmx2(bF[ni], sBb + SWZ((uint32_t)(r * 128 + cc * 16)));
            }
#pragma unroll
            for (int mi = 0; mi < 4; mi++)
#pragma unroll
                for (int ni = 0; ni < 4; ni++)
                    mma16816(acc[mi][ni], aF[mi], bF[ni]);
        }
        __syncthreads();
    }

    // Epilogue: bias + interleaved RoPE, write bf16 to g_q / g_k.
    const int colW = wn * 32;
    const int half = colW >> 6;           // 0=q, 1=k
    __nv_bfloat16* dstBase = half ? g_k : g_q;
#pragma unroll
    for (int mi = 0; mi < 4; mi++) {
#pragma unroll
        for (int rr = 0; rr < 2; rr++) {
            const int r = rowBase + wm * 64 + mi * 16 + (lane >> 2) + rr * 8;
            const int bb = r >> 10;
            const int n = r & (SEQ - 1);
            const float fn = (float)n;
            __nv_bfloat16* drow =
                dstBase + ((size_t)(bb * HEADS + h) * SEQ + n) * HEAD_SIZE;
#pragma unroll
            for (int ni = 0; ni < 4; ni++) {
                const int col = colW + ni * 8 + (lane & 3) * 2;
                const int d0 = col & 63;
                float s, cs;
                sincosf(fn * s_inv[d0 >> 1], &s, &cs);
                const float v0 = acc[mi][ni][rr * 2 + 0] + s_bias[col];
                const float v1 = acc[mi][ni][rr * 2 + 1] + s_bias[col + 1];
                __nv_bfloat162 o;
                o.x = __float2bfloat16(v0 * cs - v1 * s);
                o.y = __float2bfloat16(v1 * cs + v0 * s);
                *(__nv_bfloat162*)(drow + d0) = o;
            }
        }
    }
}

// ---------------------------------------------------------------------------
// Kernel 2: logits tile 128x128 per CTA: D = q @ k^T, mask/causal/scale.
// Epilogue staged through smem (rows padded to 136 floats) for coalesced
// STG.128 (512B contiguous per warp instruction).
// ---------------------------------------------------------------------------
#define LPAD 136  // floats per staged row (conflict-free: stride mod 32 == 8)

__global__ void logits_kernel(const float* __restrict__ mask,
                              float* __restrict__ out) {
    __shared__ __align__(128) char sbuf[64 * LPAD * 4];  // 34816 B; tiles overlap
    __shared__ float s_mk[128];

    __nv_bfloat16* sQ = (__nv_bfloat16*)sbuf;             // 16KB
    __nv_bfloat16* sK = (__nv_bfloat16*)(sbuf + 16384);   // 16KB
    float* fbuf = (float*)sbuf;                           // reused post-mma

    const int tid = threadIdx.x;
    const int lane = tid & 31;
    const int wid = tid >> 5;
    const int wm = wid & 1;
    const int wn = wid >> 1;
    const int z = blockIdx.z;
    const int b = z / HEADS;
    const int m0 = blockIdx.y << 7;
    const int n0 = blockIdx.x << 7;

    const __nv_bfloat16* qsrc = g_q + ((size_t)z * SEQ + m0) * HEAD_SIZE;
    const __nv_bfloat16* ksrc = g_k + ((size_t)z * SEQ + n0) * HEAD_SIZE;

#pragma unroll
    for (int i = 0; i < 4; i++) {
        int e = tid + i * 256;
        uint32_t so = SWZ((uint32_t)(e * 16));
        *(uint4*)((char*)sQ + so) = ((const uint4*)qsrc)[e];
        *(uint4*)((char*)sK + so) = ((const uint4*)ksrc)[e];
    }
    if (tid < 128) s_mk[tid] = mask[(size_t)b * SEQ + n0 + tid];
    __syncthreads();

    const uint32_t sQb = smem_u32(sQ);
    const uint32_t sKb = smem_u32(sK);

    float acc[4][4][4] = {};
#pragma unroll
    for (int ks = 0; ks < 4; ks++) {
        uint32_t aF[4][4], bF[4][2];
#pragma unroll
        for (int mi = 0; mi < 4; mi++) {
            int r = wm * 64 + mi * 16 + (lane & 15);
            int cc = ks * 2 + (lane >> 4);
            ldmx4(aF[mi], sQb + SWZ((uint32_t)(r * 128 + cc * 16)));
        }
#pragma unroll
        for (int ni = 0; ni < 4; ni++) {
            int l = lane & 15;
            int r = wn * 32 + ni * 8 + (l & 7);
            int cc = ks * 2 + (l >> 3);
            ldmx2(bF[ni], sKb + SWZ((uint32_t)(r * 128 + cc * 16)));
        }
#pragma unroll
        for (int mi = 0; mi < 4; mi++)
#pragma unroll
            for (int ni = 0; ni < 4; ni++)
                mma16816(acc[mi][ni], aF[mi], bF[ni]);
    }
    __syncthreads();  // tiles no longer needed; smem is reused below

    // Epilogue in two row-halves of 64: regs -> smem (masked) -> coalesced STG.
#pragma unroll
    for (int hf = 0; hf < 2; hf++) {
        if (wm == hf) {
#pragma unroll
            for (int mi = 0; mi < 4; mi++) {
#pragma unroll
                for (int rr = 0; rr < 2; rr++) {
                    const int lrow = mi * 16 + (lane >> 2) + rr * 8;  // 0..63
                    const int m = m0 + hf * 64 + lrow;
                    const float mq = mask[(size_t)b * SEQ + m];
                    const float rbias = NEGV * (mq - 1.0f);
#pragma unroll
                    for (int ni = 0; ni < 4; ni++) {
                        const int col = wn * 32 + ni * 8 + (lane & 3) * 2;
                        const int nn = n0 + col;
                        float2 o;
#pragma unroll
                        for (int q = 0; q < 2; q++) {
                            const float mk = s_mk[col + q];
                            float v = acc[mi][ni][rr * 2 + q];
                            v = v * mq + rbias;
                            v = v * mk + NEGV * (mk - 1.0f);
                            if (m > nn + q) v -= NEGV;
                            (&o.x)[q] = v * 0.125f;
                        }
                        *(float2*)(fbuf + lrow * LPAD + col) = o;
                    }
                }
            }
        }
        __syncthreads();
        // Coalesced stores: 64 rows x 128 cols = 2048 float4.
#pragma unroll
        for (int i = 0; i < 8; i++) {
            const int e = tid + i * 256;
            const int row = e >> 5;
            const int cg = (e & 31) * 4;
            float4 v = *(float4*)(fbuf + row * LPAD + cg);
            *(float4*)(out + ((size_t)z * SEQ + m0 + hf * 64 + row) * SEQ + n0 + cg) = v;
        }
        __syncthreads();
    }
}

// ---------------------------------------------------------------------------
extern "C" void kernel_launch(void* const* d_in, const int* in_sizes, int n_in,
                              void* d_out, int out_size) {
    const float* x = (const float*)d_in[0];
    const float* W = (const float*)d_in[1];
    const float* bias = (const float*)d_in[2];
    const float* mask = (const float*)d_in[3];
    float* out = (float*)d_out;

    static int smem_set = 0;
    if (!smem_set) {
        cudaFuncSetAttribute(proj_kernel,
                             cudaFuncAttributeMaxDynamicSharedMemorySize,
                             PROJ_SMEM);
        smem_set = 1;
    }

    conv_x_kernel<<<(NB * SEQ * HIDDEN / 4) / 256, 256>>>(x);
    conv_wt_kernel<<<dim3(EPROJ / 32, HIDDEN / 32), dim3(32, 8)>>>(W);

    proj_kernel<<<dim3(EPROJ / 128, NB * SEQ / 128), 256, PROJ_SMEM>>>(bias);

    logits_kernel<<<dim3(SEQ / 128, SEQ / 128, NB * HEADS), 256>>>(mask, out);
}

// round 5
// speedup vs baseline: 1.0552x; 1.0552x over previous
#include <cuda_runtime.h>
#include <cuda_bf16.h>
#include <stdint.h>
#include <math.h>

#define HEADS 12
#define HEAD_SIZE 64
#define HIDDEN 768
#define EPROJ 1536
#define SEQ 1024
#define NB 8
#define NEGV 1000000000000.0f

// bf16 staging buffers
__device__ __align__(128) __nv_bfloat16 g_xb[NB * SEQ * HIDDEN];   // [8192][768]
__device__ __align__(128) __nv_bfloat16 g_wt[EPROJ * HIDDEN];      // [1536][768] = W^T
__device__ __align__(128) __nv_bfloat16 g_q[NB * HEADS * SEQ * HEAD_SIZE];
__device__ __align__(128) __nv_bfloat16 g_k[NB * HEADS * SEQ * HEAD_SIZE];

#define SWZ(o) ((o) ^ (((o) >> 3) & 0x70))

__device__ __forceinline__ uint32_t smem_u32(const void* p) {
    uint32_t a;
    asm("{ .reg .u64 t; cvta.to.shared.u64 t, %1; cvt.u32.u64 %0, t; }"
        : "=r"(a) : "l"(p));
    return a;
}

__device__ __forceinline__ void ldmx4(uint32_t* r, uint32_t addr) {
    asm volatile("ldmatrix.sync.aligned.m8n8.x4.shared.b16 {%0,%1,%2,%3}, [%4];"
                 : "=r"(r[0]), "=r"(r[1]), "=r"(r[2]), "=r"(r[3]) : "r"(addr));
}
__device__ __forceinline__ void ldmx2(uint32_t* r, uint32_t addr) {
    asm volatile("ldmatrix.sync.aligned.m8n8.x2.shared.b16 {%0,%1}, [%2];"
                 : "=r"(r[0]), "=r"(r[1]) : "r"(addr));
}
__device__ __forceinline__ void mma16816(float* c, const uint32_t* a,
                                         const uint32_t* b) {
    asm volatile(
        "mma.sync.aligned.m16n8k16.row.col.f32.bf16.bf16.f32 "
        "{%0,%1,%2,%3}, {%4,%5,%6,%7}, {%8,%9}, {%0,%1,%2,%3};"
        : "+f"(c[0]), "+f"(c[1]), "+f"(c[2]), "+f"(c[3])
        : "r"(a[0]), "r"(a[1]), "r"(a[2]), "r"(a[3]), "r"(b[0]), "r"(b[1]));
}

// ---------------------------------------------------------------------------
// conversion kernels
// ---------------------------------------------------------------------------
__global__ void conv_x_kernel(const float* __restrict__ x) {
    int i = blockIdx.x * blockDim.x + threadIdx.x;  // float4 index
    float4 v = ((const float4*)x)[i];
    __nv_bfloat162 lo, hi;
    lo.x = __float2bfloat16(v.x); lo.y = __float2bfloat16(v.y);
    hi.x = __float2bfloat16(v.z); hi.y = __float2bfloat16(v.w);
    uint2 u;
    u.x = *(uint32_t*)&lo; u.y = *(uint32_t*)&hi;
    ((uint2*)g_xb)[i] = u;
}

__global__ void conv_wt_kernel(const float* __restrict__ W) {
    __shared__ float t[32][33];
    int bx = blockIdx.x * 32, by = blockIdx.y * 32;
#pragma unroll
    for (int j = 0; j < 4; j++)
        t[threadIdx.y + j * 8][threadIdx.x] =
            W[(size_t)(by + threadIdx.y + j * 8) * EPROJ + bx + threadIdx.x];
    __syncthreads();
#pragma unroll
    for (int j = 0; j < 4; j++)
        g_wt[(size_t)(bx + threadIdx.y + j * 8) * HIDDEN + by + threadIdx.x] =
            __float2bfloat16(t[threadIdx.x][threadIdx.y + j * 8]);
}

// ---------------------------------------------------------------------------
// Kernel 1: proj = x @ W (+bias) then RoPE -> g_q / g_k (bf16)
// CTA tile 128x128, K staged in chunks of 64. 8 warps: 2(m) x 4(n), warp
// tile 64x32. (R3 form — measured ~88% of SIMT-HMMA ceiling.)
// ---------------------------------------------------------------------------
__global__ void proj_kernel(const float* __restrict__ bias) {
    __shared__ __align__(128) __nv_bfloat16 sA[128 * 64];  // [m][k] 128B rows
    __shared__ __align__(128) __nv_bfloat16 sB[128 * 64];  // [n][k]
    __shared__ float s_inv[32];
    __shared__ float s_bias[128];

    const int tid = threadIdx.x;
    const int lane = tid & 31;
    const int wid = tid >> 5;
    const int wm = wid & 1;   // 0..1
    const int wn = wid >> 1;  // 0..3
    const int h = blockIdx.x;             // head tile (12)
    const int rowBase = blockIdx.y * 128; // token rows
    const int colBase = h * 128;

    if (tid < 32) s_inv[tid] = exp2f(-(float)(2 * tid) * (13.287712379549449f / 64.0f));
    if (tid < 128) s_bias[tid] = bias[colBase + tid];

    const uint32_t sAb = smem_u32(sA);
    const uint32_t sBb = smem_u32(sB);

    float acc[4][4][4] = {};

    for (int ch = 0; ch < 12; ch++) {
        const int k0 = ch * 64;
        __syncthreads();
#pragma unroll
        for (int i = 0; i < 4; i++) {
            int e = tid + i * 256;   // uint4 index, 1024 per tile
            int r = e >> 3;
            int c = e & 7;
            uint32_t so = SWZ((uint32_t)(r * 128 + c * 16));
            *(uint4*)((char*)sA + so) =
                *(const uint4*)(g_xb + (size_t)(rowBase + r) * HIDDEN + k0 + c * 8);
            *(uint4*)((char*)sB + so) =
                *(const uint4*)(g_wt + (size_t)(colBase + r) * HIDDEN + k0 + c * 8);
        }
        __syncthreads();

#pragma unroll
        for (int ks = 0; ks < 4; ks++) {
            uint32_t aF[4][4], bF[4][2];
#pragma unroll
            for (int mi = 0; mi < 4; mi++) {
                int r = wm * 64 + mi * 16 + (lane & 15);
                int cc = ks * 2 + (lane >> 4);
                ldmx4(aF[mi], sAb + SWZ((uint32_t)(r * 128 + cc * 16)));
            }
#pragma unroll
            for (int ni = 0; ni < 4; ni++) {
                int l = lane & 15;
                int r = wn * 32 + ni * 8 + (l & 7);
                int cc = ks * 2 + (l >> 3);
                ldmx2(bF[ni], sBb + SWZ((uint32_t)(r * 128 + cc * 16)));
            }
#pragma unroll
            for (int mi = 0; mi < 4; mi++)
#pragma unroll
                for (int ni = 0; ni < 4; ni++)
                    mma16816(acc[mi][ni], aF[mi], bF[ni]);
        }
    }

    // Epilogue: bias + interleaved RoPE, write bf16 to g_q / g_k.
    const int colW = wn * 32;
    const int half = colW >> 6;           // 0=q, 1=k
    __nv_bfloat16* dstBase = half ? g_k : g_q;
#pragma unroll
    for (int mi = 0; mi < 4; mi++) {
#pragma unroll
        for (int rr = 0; rr < 2; rr++) {
            const int r = rowBase + wm * 64 + mi * 16 + (lane >> 2) + rr * 8;
            const int bb = r >> 10;
            const int n = r & (SEQ - 1);
            const float fn = (float)n;
            __nv_bfloat16* drow =
                dstBase + ((size_t)(bb * HEADS + h) * SEQ + n) * HEAD_SIZE;
#pragma unroll
            for (int ni = 0; ni < 4; ni++) {
                const int col = colW + ni * 8 + (lane & 3) * 2;
                const int d0 = col & 63;
                float s, cs;
                sincosf(fn * s_inv[d0 >> 1], &s, &cs);
                const float v0 = acc[mi][ni][rr * 2 + 0] + s_bias[col];
                const float v1 = acc[mi][ni][rr * 2 + 1] + s_bias[col + 1];
                __nv_bfloat162 o;
                o.x = __float2bfloat16(v0 * cs - v1 * s);
                o.y = __float2bfloat16(v1 * cs + v0 * s);
                *(__nv_bfloat162*)(drow + d0) = o;
            }
        }
    }
}

// ---------------------------------------------------------------------------
// Kernel 2: logits tile 128x128 per CTA: D = q @ k^T, mask/causal/scale.
// Epilogue: ONE __syncthreads, then warp-private 2KB staging slots (reusing
// the dead Q-tile smem); write masked frags -> __syncwarp -> coalesced
// STG.128 (each instr = 4 rows x 128B full lines).
// ---------------------------------------------------------------------------
__global__ void logits_kernel(const float* __restrict__ mask,
                              float* __restrict__ out) {
    __shared__ __align__(128) __nv_bfloat16 sQ[128 * 64];  // 16KB (reused)
    __shared__ __align__(128) __nv_bfloat16 sK[128 * 64];  // 16KB
    __shared__ float s_mk[128];

    const int tid = threadIdx.x;
    const int lane = tid & 31;
    const int wid = tid >> 5;
    const int wm = wid & 1;
    const int wn = wid >> 1;
    const int z = blockIdx.z;
    const int b = z / HEADS;
    const int m0 = blockIdx.y << 7;
    const int n0 = blockIdx.x << 7;

    const __nv_bfloat16* qsrc = g_q + ((size_t)z * SEQ + m0) * HEAD_SIZE;
    const __nv_bfloat16* ksrc = g_k + ((size_t)z * SEQ + n0) * HEAD_SIZE;

#pragma unroll
    for (int i = 0; i < 4; i++) {
        int e = tid + i * 256;
        uint32_t so = SWZ((uint32_t)(e * 16));
        *(uint4*)((char*)sQ + so) = ((const uint4*)qsrc)[e];
        *(uint4*)((char*)sK + so) = ((const uint4*)ksrc)[e];
    }
    if (tid < 128) s_mk[tid] = mask[(size_t)b * SEQ + n0 + tid];
    __syncthreads();

    const uint32_t sQb = smem_u32(sQ);
    const uint32_t sKb = smem_u32(sK);

    float acc[4][4][4] = {};
#pragma unroll
    for (int ks = 0; ks < 4; ks++) {
        uint32_t aF[4][4], bF[4][2];
#pragma unroll
        for (int mi = 0; mi < 4; mi++) {
            int r = wm * 64 + mi * 16 + (lane & 15);
            int cc = ks * 2 + (lane >> 4);
            ldmx4(aF[mi], sQb + SWZ((uint32_t)(r * 128 + cc * 16)));
        }
#pragma unroll
        for (int ni = 0; ni < 4; ni++) {
            int l = lane & 15;
            int r = wn * 32 + ni * 8 + (l & 7);
            int cc = ks * 2 + (l >> 3);
            ldmx2(bF[ni], sKb + SWZ((uint32_t)(r * 128 + cc * 16)));
        }
#pragma unroll
        for (int mi = 0; mi < 4; mi++)
#pragma unroll
            for (int ni = 0; ni < 4; ni++)
                mma16816(acc[mi][ni], aF[mi], bF[ni]);
    }
    __syncthreads();  // tiles dead; smem reused as warp-private staging

    // Warp-private 2KB slot inside the (dead) sQ region: 16 rows x 128B, SW128.
    const uint32_t slot = sQb + wid * 2048;

#pragma unroll
    for (int mi = 0; mi < 4; mi++) {
        // Phase A: mask/causal/scale + STS into slot.
#pragma unroll
        for (int rr = 0; rr < 2; rr++) {
            const int lrow = (lane >> 2) + rr * 8;      // 0..15
            const int m = m0 + wm * 64 + mi * 16 + lrow;
            const float mq = mask[(size_t)b * SEQ + m];
            const float rbias = NEGV * (mq - 1.0f);
#pragma unroll
            for (int ni = 0; ni < 4; ni++) {
                const int col = wn * 32 + ni * 8 + (lane & 3) * 2;  // 0..127
                const int lcol = ni * 8 + (lane & 3) * 2;           // 0..31
                const int nn = n0 + col;
                float2 o;
#pragma unroll
                for (int q = 0; q < 2; q++) {
                    const float mk = s_mk[col + q];
                    float v = acc[mi][ni][rr * 2 + q];
                    v = v * mq + rbias;
                    v = v * mk + NEGV * (mk - 1.0f);
                    if (m > nn + q) v -= NEGV;
                    (&o.x)[q] = v * 0.125f;
                }
                uint32_t off = (uint32_t)(lrow * 128 + lcol * 4);
                asm volatile("st.shared.v2.f32 [%0], {%1, %2};"
                             :: "r"(slot + SWZ(off)), "f"(o.x), "f"(o.y)
                             : "memory");
            }
        }
        __syncwarp();
        // Phase B: coalesced stores — 16 rows x 32 cols = 128 float4.
#pragma unroll
        for (int t = 0; t < 4; t++) {
            const int row = t * 4 + (lane >> 3);        // 0..15
            const int colf = (lane & 7) * 4;            // 0..28
            uint32_t off = (uint32_t)(row * 128 + colf * 4);
            float4 v;
            asm volatile("ld.shared.v4.f32 {%0,%1,%2,%3}, [%4];"
                         : "=f"(v.x), "=f"(v.y), "=f"(v.z), "=f"(v.w)
                         : "r"(slot + SWZ(off)));
            *(float4*)(out + ((size_t)z * SEQ + m0 + wm * 64 + mi * 16 + row) * SEQ
                       + n0 + wn * 32 + colf) = v;
        }
        __syncwarp();
    }
}

// ---------------------------------------------------------------------------
extern "C" void kernel_launch(void* const* d_in, const int* in_sizes, int n_in,
                              void* d_out, int out_size) {
    const float* x = (const float*)d_in[0];
    const float* W = (const float*)d_in[1];
    const float* bias = (const float*)d_in[2];
    const float* mask = (const float*)d_in[3];
    float* out = (float*)d_out;

    conv_x_kernel<<<(NB * SEQ * HIDDEN / 4) / 256, 256>>>(x);
    conv_wt_kernel<<<dim3(EPROJ / 32, HIDDEN / 32), dim3(32, 8)>>>(W);

    proj_kernel<<<dim3(EPROJ / 128, NB * SEQ / 128), 256>>>(bias);

    logits_kernel<<<dim3(SEQ / 128, SEQ / 128, NB * HEADS), 256>>>(mask, out);
}